// round 13
// baseline (speedup 1.0000x reference)
#include <cuda_runtime.h>
#include <cuda_bf16.h>

// Token-conditioned tables: hs depends only on token id (V=64).
__device__ float g_hs_table[64 * 64];
__device__ float g_gram[64 * 64];     // gram[u][v] = hs_u . hs_v

#define H      64
#define VOCAB  64
#define INNER  16
#define LSEQ   2048
#define TSTEPS 1023
#define LRATE  0.01f
#define C2H    (2.0f / 64.0f)

#define CPB    8          // chains (warps) per block -> 2 warps per SMSP
#define NTHR   (CPB * 32)

#define SHX(v, m) __shfl_xor_sync(0xffffffffu, (v), (m))

// ---------------------------------------------------------------------------
// Kernel A: build hs_table[v][h] = LayerNorm(e + FF(e)) for each vocab id v.
// ---------------------------------------------------------------------------
__global__ void build_table_kernel(
    const float* __restrict__ embed,   // (64,64)
    const float* __restrict__ ff_w1,   // (64,128)
    const float* __restrict__ ff_b1,   // (128,)
    const float* __restrict__ ff_w2,   // (128,64)
    const float* __restrict__ ff_b2,   // (64,)
    const float* __restrict__ ln_g,    // (64,)
    const float* __restrict__ ln_b)    // (64,)
{
    __shared__ float e_sh[64];
    __shared__ float u_sh[128];
    __shared__ float h_sh[64];

    const int v = blockIdx.x;
    const int t = threadIdx.x;

    if (t < 64) e_sh[t] = embed[v * 64 + t];
    __syncthreads();

    {
        float acc = ff_b1[t];
        #pragma unroll 8
        for (int h = 0; h < 64; ++h)
            acc = fmaf(e_sh[h], ff_w1[h * 128 + t], acc);
        u_sh[t] = fmaxf(acc, 0.0f);
    }
    __syncthreads();

    if (t < 64) {
        float acc = ff_b2[t];
        #pragma unroll 8
        for (int i = 0; i < 128; ++i)
            acc = fmaf(u_sh[i], ff_w2[i * 64 + t], acc);
        h_sh[t] = e_sh[t] + acc;
    }
    __syncthreads();

    if (t < 64) {
        float mu = 0.0f;
        #pragma unroll 8
        for (int h = 0; h < 64; ++h) mu += h_sh[h];
        mu *= (1.0f / 64.0f);
        float var = 0.0f;
        #pragma unroll 8
        for (int h = 0; h < 64; ++h) {
            float d = h_sh[h] - mu;
            var = fmaf(d, d, var);
        }
        var *= (1.0f / 64.0f);
        const float inv = rsqrtf(var + 1e-5f);
        g_hs_table[v * 64 + t] = (h_sh[t] - mu) * inv * ln_g[t] + ln_b[t];
    }
}

// ---------------------------------------------------------------------------
// Kernel A2: gram[u][v] = hs_u . hs_v.  grid(64), block(64)
// ---------------------------------------------------------------------------
__global__ void gram_kernel()
{
    __shared__ float T[VOCAB * H];
    const int u = blockIdx.x;
    const int v = threadIdx.x;
    for (int i = v; i < VOCAB * H; i += 64) T[i] = g_hs_table[i];
    __syncthreads();
    float acc = 0.0f;
    #pragma unroll 8
    for (int h = 0; h < H; ++h)
        acc = fmaf(T[u * H + h], T[v * H + h], acc);
    g_gram[u * 64 + v] = acc;
}

// ---------------------------------------------------------------------------
// Kernel B: per-batch TTT chain; Gram lookahead + permuted halving reductions.
// One warp per chain, 8 warps/block -> 2 warps per SMSP (latency hiding).
// grid(32), block(256)
// Lane ℓ reg m holds absolute index jown^m, jown = (ℓ>>1)&15.
// ---------------------------------------------------------------------------
__global__ void __launch_bounds__(NTHR, 1) ttt_kernel(
    const int*   __restrict__ seq,     // (256, 2048) int32
    const float* __restrict__ w1,      // (64,16)
    const float* __restrict__ b1,      // (16,)
    const float* __restrict__ w2,      // (16,64)
    const float* __restrict__ b2,      // (64,)
    const float* __restrict__ out_w,   // (64,64)
    const float* __restrict__ out_b,   // (64,)
    float*       __restrict__ out)     // (256,64)
{
    __shared__ float         tab[VOCAB * H];     // 16 KB
    __shared__ float         gram[VOCAB * 64];   // 16 KB
    __shared__ unsigned char tokb[CPB * LSEQ];   // 16 KB
    __shared__ float         ctx_sh[CPB][H];

    const int tid  = threadIdx.x;
    const int wid  = tid >> 5;
    const int t    = tid & 31;
    const int b    = blockIdx.x * CPB + wid;
    const int jown = (t >> 1) & 15;              // per-lane XOR permutation base

    // Cooperative staging
    for (int i = tid; i < VOCAB * H; i += NTHR) {
        tab[i]  = g_hs_table[i];
        gram[i] = g_gram[i];
    }
    const int* sbase = seq + (size_t)blockIdx.x * CPB * LSEQ;
    for (int i = tid; i < CPB * LSEQ; i += NTHR)
        tokb[i] = (unsigned char)sbase[i];

    // Load initial parameters in per-lane permuted j-order (j = jown ^ m)
    float W1a[INNER], W1b[INNER], W2a[INNER], W2b[INNER], b1r[INNER];
    #pragma unroll
    for (int m = 0; m < INNER; ++m) {
        const int j = jown ^ m;
        W1a[m] = w1[t * INNER + j];
        W1b[m] = w1[(t + 32) * INNER + j];
        W2a[m] = w2[j * H + t];
        W2b[m] = w2[j * H + t + 32];
        b1r[m] = b1[j];
    }
    float b2a = b2[t];
    float b2b = b2[t + 32];

    __syncthreads();

    // Patch: slot 2046 (unused k of would-be step 1023) <- query token 2047,
    // so the last lookahead computes the final-forward z for free.
    if (tid < CPB) tokb[tid * LSEQ + (LSEQ - 2)] = tokb[tid * LSEQ + (LSEQ - 1)];
    __syncthreads();

    const unsigned char* myt = tokb + wid * LSEQ;

    float zs[INNER], a[INNER], p[INNER];

    // ---- prologue: zs = W1_0^T k_0 (permuted reduce + gather) ----
    int   tk = myt[0];
    float k0 = tab[tk * H + t];
    float k1 = tab[tk * H + t + 32];
    #pragma unroll
    for (int m = 0; m < INNER; ++m)
        zs[m] = fmaf(k0, W1a[m], k1 * W1b[m]);
    #pragma unroll
    for (int m = 0; m < 8; ++m) zs[m] += SHX(zs[m ^ 8], 16);
    #pragma unroll
    for (int m = 0; m < 4; ++m) zs[m] += SHX(zs[m ^ 4], 8);
    #pragma unroll
    for (int m = 0; m < 2; ++m) zs[m] += SHX(zs[m ^ 2], 4);
    zs[0] += SHX(zs[1], 2);
    zs[0] += SHX(zs[0], 1);
    zs[1] = SHX(zs[0], 2);
    #pragma unroll
    for (int m = 0; m < 2; ++m) zs[2 + m] = SHX(zs[m], 4);
    #pragma unroll
    for (int m = 0; m < 4; ++m) zs[4 + m] = SHX(zs[m], 8);
    #pragma unroll
    for (int m = 0; m < 8; ++m) zs[8 + m] = SHX(zs[m], 16);

    #pragma unroll 1
    for (int s = 0; s < TSTEPS; ++s) {
        const int tv = myt[2 * s + 1];
        const int tn = myt[2 * s + 2];           // next k (or query at s=1022)
        const float v0  = tab[tv * H + t];
        const float v1  = tab[tv * H + t + 32];
        const float kn0 = tab[tn * H + t];
        const float kn1 = tab[tn * H + t + 32];
        const float gkk = gram[tk * 64 + tn];    // k_s . k_{s+1}

        // ---- a = relu(z + b1) ----
        #pragma unroll
        for (int m = 0; m < INNER; ++m)
            a[m] = fmaxf(zs[m] + b1r[m], 0.0f);

        // ---- pred[h] = b2[h] + sum_j a[j] W2[j,h] (lane-local, 4 accums) ----
        float p0a = b2a, p0b = 0.0f, p0c = 0.0f, p0d = 0.0f;
        float p1a = b2b, p1b = 0.0f, p1c = 0.0f, p1d = 0.0f;
        #pragma unroll
        for (int m = 0; m < INNER; m += 4) {
            p0a = fmaf(a[m],     W2a[m],     p0a);
            p0b = fmaf(a[m + 1], W2a[m + 1], p0b);
            p0c = fmaf(a[m + 2], W2a[m + 2], p0c);
            p0d = fmaf(a[m + 3], W2a[m + 3], p0d);
            p1a = fmaf(a[m],     W2b[m],     p1a);
            p1b = fmaf(a[m + 1], W2b[m + 1], p1b);
            p1c = fmaf(a[m + 2], W2b[m + 2], p1c);
            p1d = fmaf(a[m + 3], W2b[m + 3], p1d);
        }
        const float d0 = C2H * (((p0a + p0b) + (p0c + p0d)) - v0);
        const float d1 = C2H * (((p1a + p1b) + (p1c + p1d)) - v1);

        // ---- partials: da (old W2) and next-z (old W1, pre-update) ----
        #pragma unroll
        for (int m = 0; m < INNER; ++m) {
            p[m]  = fmaf(d0,  W2a[m], d1  * W2b[m]);
            zs[m] = fmaf(kn0, W1a[m], kn1 * W1b[m]);
        }

        // ---- two interleaved permuted all-reduces (31 SHFL + 16 ADD each) ----
        #pragma unroll
        for (int m = 0; m < 8; ++m) p[m]  += SHX(p[m ^ 8], 16);
        #pragma unroll
        for (int m = 0; m < 8; ++m) zs[m] += SHX(zs[m ^ 8], 16);
        #pragma unroll
        for (int m = 0; m < 4; ++m) p[m]  += SHX(p[m ^ 4], 8);
        #pragma unroll
        for (int m = 0; m < 4; ++m) zs[m] += SHX(zs[m ^ 4], 8);
        #pragma unroll
        for (int m = 0; m < 2; ++m) p[m]  += SHX(p[m ^ 2], 4);
        #pragma unroll
        for (int m = 0; m < 2; ++m) zs[m] += SHX(zs[m ^ 2], 4);
        p[0]  += SHX(p[1], 2);
        zs[0] += SHX(zs[1], 2);
        p[0]  += SHX(p[0], 1);
        zs[0] += SHX(zs[0], 1);
        // gather back to permuted-full
        p[1]  = SHX(p[0], 2);
        zs[1] = SHX(zs[0], 2);
        #pragma unroll
        for (int m = 0; m < 2; ++m) { p[2 + m] = SHX(p[m], 4);  zs[2 + m] = SHX(zs[m], 4); }
        #pragma unroll
        for (int m = 0; m < 4; ++m) { p[4 + m] = SHX(p[m], 8);  zs[4 + m] = SHX(zs[m], 8); }
        #pragma unroll
        for (int m = 0; m < 8; ++m) { p[8 + m] = SHX(p[m], 16); zs[8 + m] = SHX(zs[m], 16); }

        // ---- update W2, b2: dW2[j,h] = a[j]*d[h] ----
        const float l0 = LRATE * d0;
        const float l1 = LRATE * d1;
        #pragma unroll
        for (int m = 0; m < INNER; ++m) {
            W2a[m] = fmaf(-l0, a[m], W2a[m]);
            W2b[m] = fmaf(-l1, a[m], W2b[m]);
        }
        b2a -= l0;
        b2b -= l1;

        // ---- dz; update W1, b1; correct looked-ahead z with Gram rank-1 ----
        const float m0 = LRATE * k0;
        const float m1 = LRATE * k1;
        const float gl = LRATE * gkk;
        #pragma unroll
        for (int m = 0; m < INNER; ++m) {
            const float dz = (a[m] > 0.0f) ? p[m] : 0.0f;
            W1a[m] = fmaf(-m0, dz, W1a[m]);
            W1b[m] = fmaf(-m1, dz, W1b[m]);
            b1r[m] = fmaf(-LRATE, dz, b1r[m]);
            zs[m]  = fmaf(-gl, dz, zs[m]);
        }

        k0 = kn0; k1 = kn1; tk = tn;
    }

    // ---- final forward: zs already holds W1_final^T q ----
    {
        #pragma unroll
        for (int m = 0; m < INNER; ++m)
            a[m] = fmaxf(zs[m] + b1r[m], 0.0f);

        float c0 = b2a, c1 = b2b;
        #pragma unroll
        for (int m = 0; m < INNER; ++m) {
            c0 = fmaf(a[m], W2a[m], c0);
            c1 = fmaf(a[m], W2b[m], c1);
        }
        ctx_sh[wid][t]      = c0;
        ctx_sh[wid][t + 32] = c1;
    }
    __syncwarp();

    // out[b, o] = out_b[o] + sum_h ctx[h] * out_w[h, o]
    #pragma unroll
    for (int half = 0; half < 2; ++half) {
        const int o = t + half * 32;
        float acc = out_b[o];
        #pragma unroll 8
        for (int h = 0; h < H; ++h)
            acc = fmaf(ctx_sh[wid][h], out_w[h * 64 + o], acc);
        out[b * 64 + o] = acc;
    }
}

// ---------------------------------------------------------------------------
// Launch
// Inputs (metadata order): 0 seq(i32), 1 embed, 2 ff_w1, 3 ff_b1, 4 ff_w2,
// 5 ff_b2, 6 ln_g, 7 ln_b, 8 w1, 9 b1, 10 w2, 11 b2, 12 out_w, 13 out_b
// ---------------------------------------------------------------------------
extern "C" void kernel_launch(void* const* d_in, const int* in_sizes, int n_in,
                              void* d_out, int out_size)
{
    const int*   seq    = (const int*)  d_in[0];
    const float* embed  = (const float*)d_in[1];
    const float* ff_w1  = (const float*)d_in[2];
    const float* ff_b1  = (const float*)d_in[3];
    const float* ff_w2  = (const float*)d_in[4];
    const float* ff_b2  = (const float*)d_in[5];
    const float* ln_g   = (const float*)d_in[6];
    const float* ln_b   = (const float*)d_in[7];
    const float* w1     = (const float*)d_in[8];
    const float* b1     = (const float*)d_in[9];
    const float* w2     = (const float*)d_in[10];
    const float* b2     = (const float*)d_in[11];
    const float* out_w  = (const float*)d_in[12];
    const float* out_b  = (const float*)d_in[13];
    float*       out    = (float*)d_out;

    build_table_kernel<<<64, 128>>>(embed, ff_w1, ff_b1, ff_w2, ff_b2, ln_g, ln_b);
    gram_kernel<<<64, 64>>>();
    ttt_kernel<<<256 / CPB, NTHR>>>(seq, w1, b1, w2, b2, out_w, out_b, out);
}

// round 14
// speedup vs baseline: 1.7801x; 1.7801x over previous
#include <cuda_runtime.h>
#include <cuda_bf16.h>

// Token-conditioned tables: hs depends only on token id (V=64).
__device__ float g_hs_table[64 * 64];
__device__ float g_gram[64 * 64];     // gram[u][v] = hs_u . hs_v

#define H      64
#define VOCAB  64
#define INNER  16
#define LSEQ   2048
#define TSTEPS 1023
#define LRATE  0.01f
#define C2H    (2.0f / 64.0f)

#define CPB    2          // chains (warps) per block
#define NTHR   (CPB * 32)

#define SHX(v, m) __shfl_xor_sync(0xffffffffu, (v), (m))

// ---- packed f32x2 helpers (Blackwell sm_103a; PTX-only FFMA2 path) ----
typedef unsigned long long f32x2;
__device__ __forceinline__ f32x2 pk(float lo, float hi) {
    f32x2 r; asm("mov.b64 %0, {%1, %2};" : "=l"(r) : "f"(lo), "f"(hi)); return r;
}
__device__ __forceinline__ void unpk(f32x2 v, float& lo, float& hi) {
    asm("mov.b64 {%0, %1}, %2;" : "=f"(lo), "=f"(hi) : "l"(v));
}
__device__ __forceinline__ f32x2 fma2(f32x2 a, f32x2 b, f32x2 c) {
    f32x2 r; asm("fma.rn.f32x2 %0, %1, %2, %3;" : "=l"(r) : "l"(a), "l"(b), "l"(c)); return r;
}
__device__ __forceinline__ f32x2 mul2(f32x2 a, f32x2 b) {
    f32x2 r; asm("mul.rn.f32x2 %0, %1, %2;" : "=l"(r) : "l"(a), "l"(b)); return r;
}
__device__ __forceinline__ f32x2 add2(f32x2 a, f32x2 b) {
    f32x2 r; asm("add.rn.f32x2 %0, %1, %2;" : "=l"(r) : "l"(a), "l"(b)); return r;
}

// ---------------------------------------------------------------------------
// Kernel A: build hs_table[v][h] = LayerNorm(e + FF(e)) for each vocab id v.
// ---------------------------------------------------------------------------
__global__ void build_table_kernel(
    const float* __restrict__ embed,   // (64,64)
    const float* __restrict__ ff_w1,   // (64,128)
    const float* __restrict__ ff_b1,   // (128,)
    const float* __restrict__ ff_w2,   // (128,64)
    const float* __restrict__ ff_b2,   // (64,)
    const float* __restrict__ ln_g,    // (64,)
    const float* __restrict__ ln_b)    // (64,)
{
    __shared__ float e_sh[64];
    __shared__ float u_sh[128];
    __shared__ float h_sh[64];

    const int v = blockIdx.x;
    const int t = threadIdx.x;

    if (t < 64) e_sh[t] = embed[v * 64 + t];
    __syncthreads();

    {
        float acc = ff_b1[t];
        #pragma unroll 8
        for (int h = 0; h < 64; ++h)
            acc = fmaf(e_sh[h], ff_w1[h * 128 + t], acc);
        u_sh[t] = fmaxf(acc, 0.0f);
    }
    __syncthreads();

    if (t < 64) {
        float acc = ff_b2[t];
        #pragma unroll 8
        for (int i = 0; i < 128; ++i)
            acc = fmaf(u_sh[i], ff_w2[i * 64 + t], acc);
        h_sh[t] = e_sh[t] + acc;
    }
    __syncthreads();

    if (t < 64) {
        float mu = 0.0f;
        #pragma unroll 8
        for (int h = 0; h < 64; ++h) mu += h_sh[h];
        mu *= (1.0f / 64.0f);
        float var = 0.0f;
        #pragma unroll 8
        for (int h = 0; h < 64; ++h) {
            float d = h_sh[h] - mu;
            var = fmaf(d, d, var);
        }
        var *= (1.0f / 64.0f);
        const float inv = rsqrtf(var + 1e-5f);
        g_hs_table[v * 64 + t] = (h_sh[t] - mu) * inv * ln_g[t] + ln_b[t];
    }
}

// ---------------------------------------------------------------------------
// Kernel A2: gram[u][v] = hs_u . hs_v.  grid(64), block(64)
// ---------------------------------------------------------------------------
__global__ void gram_kernel()
{
    __shared__ float T[VOCAB * H];
    const int u = blockIdx.x;
    const int v = threadIdx.x;
    for (int i = v; i < VOCAB * H; i += 64) T[i] = g_hs_table[i];
    __syncthreads();
    float acc = 0.0f;
    #pragma unroll 8
    for (int h = 0; h < H; ++h)
        acc = fmaf(T[u * H + h], T[v * H + h], acc);
    g_gram[u * 64 + v] = acc;
}

// ---------------------------------------------------------------------------
// Kernel B: per-batch TTT chain; Gram lookahead + permuted halving reductions
// + packed f32x2 elementwise math. One warp per chain. grid(128), block(64)
// Lane ℓ logical index: reg m holds j = jown^m, jown=(ℓ>>1)&15; packed reg i
// holds (m=2i, m=2i+1).
// ---------------------------------------------------------------------------
__global__ void __launch_bounds__(NTHR, 1) ttt_kernel(
    const int*   __restrict__ seq,     // (256, 2048) int32
    const float* __restrict__ w1,      // (64,16)
    const float* __restrict__ b1,      // (16,)
    const float* __restrict__ w2,      // (16,64)
    const float* __restrict__ b2,      // (64,)
    const float* __restrict__ out_w,   // (64,64)
    const float* __restrict__ out_b,   // (64,)
    float*       __restrict__ out)     // (256,64)
{
    __shared__ float         tab[VOCAB * H];     // 16 KB
    __shared__ float         gram[VOCAB * 64];   // 16 KB
    __shared__ unsigned char tokb[CPB * LSEQ];   // 4 KB
    __shared__ float         ctx_sh[CPB][H];

    const int tid  = threadIdx.x;
    const int wid  = tid >> 5;
    const int t    = tid & 31;
    const int b    = blockIdx.x * CPB + wid;
    const int jown = (t >> 1) & 15;              // per-lane XOR permutation base

    // Cooperative staging
    for (int i = tid; i < VOCAB * H; i += NTHR) {
        tab[i]  = g_hs_table[i];
        gram[i] = g_gram[i];
    }
    const int* sbase = seq + (size_t)blockIdx.x * CPB * LSEQ;
    for (int i = tid; i < CPB * LSEQ; i += NTHR)
        tokb[i] = (unsigned char)sbase[i];

    // Load initial parameters, packed over (m, m+1), j = jown ^ m
    f32x2 W1aP[8], W1bP[8], W2aP[8], W2bP[8], b1rP[8];
    #pragma unroll
    for (int i = 0; i < 8; ++i) {
        const int j0 = jown ^ (2 * i);
        const int j1 = jown ^ (2 * i + 1);
        W1aP[i] = pk(w1[t * INNER + j0],        w1[t * INNER + j1]);
        W1bP[i] = pk(w1[(t + 32) * INNER + j0], w1[(t + 32) * INNER + j1]);
        W2aP[i] = pk(w2[j0 * H + t],            w2[j1 * H + t]);
        W2bP[i] = pk(w2[j0 * H + t + 32],       w2[j1 * H + t + 32]);
        b1rP[i] = pk(b1[j0],                    b1[j1]);
    }
    float b2a = b2[t];
    float b2b = b2[t + 32];
    const f32x2 nLRd = pk(-LRATE, -LRATE);

    __syncthreads();

    // Patch: slot 2046 (unused k of would-be step 1023) <- query token 2047,
    // so the last lookahead computes the final-forward z for free.
    if (tid < CPB) tokb[tid * LSEQ + (LSEQ - 2)] = tokb[tid * LSEQ + (LSEQ - 1)];
    __syncthreads();

    const unsigned char* myt = tokb + wid * LSEQ;

    float zs[INNER], x[INNER], p[INNER];
    f32x2 zsP[8], aP[8];

    // ---- prologue: zs = W1_0^T k_0 (packed partial, scalar reduce+gather) ----
    int   tk = myt[0];
    float k0 = tab[tk * H + t];
    float k1 = tab[tk * H + t + 32];
    {
        const f32x2 k0d = pk(k0, k0), k1d = pk(k1, k1);
        #pragma unroll
        for (int i = 0; i < 8; ++i) {
            f32x2 zp = fma2(k0d, W1aP[i], mul2(k1d, W1bP[i]));
            unpk(zp, zs[2 * i], zs[2 * i + 1]);
        }
    }
    #pragma unroll
    for (int m = 0; m < 8; ++m) zs[m] += SHX(zs[m ^ 8], 16);
    #pragma unroll
    for (int m = 0; m < 4; ++m) zs[m] += SHX(zs[m ^ 4], 8);
    #pragma unroll
    for (int m = 0; m < 2; ++m) zs[m] += SHX(zs[m ^ 2], 4);
    zs[0] += SHX(zs[1], 2);
    zs[0] += SHX(zs[0], 1);
    zs[1] = SHX(zs[0], 2);
    #pragma unroll
    for (int m = 0; m < 2; ++m) zs[2 + m] = SHX(zs[m], 4);
    #pragma unroll
    for (int m = 0; m < 4; ++m) zs[4 + m] = SHX(zs[m], 8);
    #pragma unroll
    for (int m = 0; m < 8; ++m) zs[8 + m] = SHX(zs[m], 16);
    #pragma unroll
    for (int i = 0; i < 8; ++i) zsP[i] = pk(zs[2 * i], zs[2 * i + 1]);

    #pragma unroll 1
    for (int s = 0; s < TSTEPS; ++s) {
        const int tv = myt[2 * s + 1];
        const int tn = myt[2 * s + 2];           // next k (or query at s=1022)
        const float v0  = tab[tv * H + t];
        const float v1  = tab[tv * H + t + 32];
        const float kn0 = tab[tn * H + t];
        const float kn1 = tab[tn * H + t + 32];
        const float gkk = gram[tk * 64 + tn];    // k_s . k_{s+1}

        // ---- x = z + b1 (packed); a = relu(x) (scalar FMNMX, alu pipe) ----
        #pragma unroll
        for (int i = 0; i < 8; ++i) {
            f32x2 xp = add2(zsP[i], b1rP[i]);
            unpk(xp, x[2 * i], x[2 * i + 1]);
            aP[i] = pk(fmaxf(x[2 * i], 0.0f), fmaxf(x[2 * i + 1], 0.0f));
        }

        // ---- pred: pr0/pr1 packed accumulators over m-pairs ----
        f32x2 pr0 = pk(b2a, 0.0f), pr1 = pk(b2b, 0.0f);
        #pragma unroll
        for (int i = 0; i < 8; ++i) {
            pr0 = fma2(aP[i], W2aP[i], pr0);
            pr1 = fma2(aP[i], W2bP[i], pr1);
        }
        float e0, e1, f0, f1;
        unpk(pr0, e0, e1);
        unpk(pr1, f0, f1);
        const float d0 = C2H * ((e0 + e1) - v0);
        const float d1 = C2H * ((f0 + f1) - v1);

        // ---- partials: da (old W2) and next-z (old W1), packed ----
        const f32x2 d0d  = pk(d0, d0),   d1d  = pk(d1, d1);
        const f32x2 kn0d = pk(kn0, kn0), kn1d = pk(kn1, kn1);
        #pragma unroll
        for (int i = 0; i < 8; ++i) {
            f32x2 pp = fma2(d0d,  W2aP[i], mul2(d1d,  W2bP[i]));
            f32x2 zp = fma2(kn0d, W1aP[i], mul2(kn1d, W1bP[i]));
            unpk(pp, p[2 * i],  p[2 * i + 1]);
            unpk(zp, zs[2 * i], zs[2 * i + 1]);
        }

        // ---- two interleaved permuted halving reduces + gathers (scalar) ----
        #pragma unroll
        for (int m = 0; m < 8; ++m) p[m]  += SHX(p[m ^ 8], 16);
        #pragma unroll
        for (int m = 0; m < 8; ++m) zs[m] += SHX(zs[m ^ 8], 16);
        #pragma unroll
        for (int m = 0; m < 4; ++m) p[m]  += SHX(p[m ^ 4], 8);
        #pragma unroll
        for (int m = 0; m < 4; ++m) zs[m] += SHX(zs[m ^ 4], 8);
        #pragma unroll
        for (int m = 0; m < 2; ++m) p[m]  += SHX(p[m ^ 2], 4);
        #pragma unroll
        for (int m = 0; m < 2; ++m) zs[m] += SHX(zs[m ^ 2], 4);
        p[0]  += SHX(p[1], 2);
        zs[0] += SHX(zs[1], 2);
        p[0]  += SHX(p[0], 1);
        zs[0] += SHX(zs[0], 1);
        p[1]  = SHX(p[0], 2);
        zs[1] = SHX(zs[0], 2);
        #pragma unroll
        for (int m = 0; m < 2; ++m) { p[2 + m] = SHX(p[m], 4);  zs[2 + m] = SHX(zs[m], 4); }
        #pragma unroll
        for (int m = 0; m < 4; ++m) { p[4 + m] = SHX(p[m], 8);  zs[4 + m] = SHX(zs[m], 8); }
        #pragma unroll
        for (int m = 0; m < 8; ++m) { p[8 + m] = SHX(p[m], 16); zs[8 + m] = SHX(zs[m], 16); }

        // ---- update W2, b2 (packed): dW2[j,h] = a[j]*d[h] ----
        const float nl0 = -LRATE * d0;
        const float nl1 = -LRATE * d1;
        const f32x2 nl0d = pk(nl0, nl0), nl1d = pk(nl1, nl1);
        #pragma unroll
        for (int i = 0; i < 8; ++i) {
            W2aP[i] = fma2(nl0d, aP[i], W2aP[i]);
            W2bP[i] = fma2(nl1d, aP[i], W2bP[i]);
        }
        b2a += nl0;
        b2b += nl1;

        // ---- dz (scalar mask); packed W1/b1 updates + Gram z-correction ----
        const f32x2 nm0d = pk(-LRATE * k0, -LRATE * k0);
        const f32x2 nm1d = pk(-LRATE * k1, -LRATE * k1);
        const f32x2 ngld = pk(-LRATE * gkk, -LRATE * gkk);
        #pragma unroll
        for (int i = 0; i < 8; ++i) {
            const float dz0 = (x[2 * i]     > 0.0f) ? p[2 * i]     : 0.0f;
            const float dz1 = (x[2 * i + 1] > 0.0f) ? p[2 * i + 1] : 0.0f;
            const f32x2 dzP = pk(dz0, dz1);
            const f32x2 zsg = pk(zs[2 * i], zs[2 * i + 1]);
            W1aP[i] = fma2(nm0d, dzP, W1aP[i]);
            W1bP[i] = fma2(nm1d, dzP, W1bP[i]);
            b1rP[i] = fma2(nLRd, dzP, b1rP[i]);
            zsP[i]  = fma2(ngld, dzP, zsg);
        }

        k0 = kn0; k1 = kn1; tk = tn;
    }

    // ---- final forward: zsP already holds W1_final^T q (packed) ----
    {
        f32x2 c0P = pk(b2a, 0.0f), c1P = pk(b2b, 0.0f);
        #pragma unroll
        for (int i = 0; i < 8; ++i) {
            f32x2 xp = add2(zsP[i], b1rP[i]);
            float x0, x1;
            unpk(xp, x0, x1);
            const f32x2 ap = pk(fmaxf(x0, 0.0f), fmaxf(x1, 0.0f));
            c0P = fma2(ap, W2aP[i], c0P);
            c1P = fma2(ap, W2bP[i], c1P);
        }
        float c0l, c0h, c1l, c1h;
        unpk(c0P, c0l, c0h);
        unpk(c1P, c1l, c1h);
        ctx_sh[wid][t]      = c0l + c0h;
        ctx_sh[wid][t + 32] = c1l + c1h;
    }
    __syncwarp();

    // out[b, o] = out_b[o] + sum_h ctx[h] * out_w[h, o]
    #pragma unroll
    for (int half = 0; half < 2; ++half) {
        const int o = t + half * 32;
        float acc = out_b[o];
        #pragma unroll 8
        for (int h = 0; h < H; ++h)
            acc = fmaf(ctx_sh[wid][h], out_w[h * 64 + o], acc);
        out[b * 64 + o] = acc;
    }
}

// ---------------------------------------------------------------------------
// Launch
// Inputs (metadata order): 0 seq(i32), 1 embed, 2 ff_w1, 3 ff_b1, 4 ff_w2,
// 5 ff_b2, 6 ln_g, 7 ln_b, 8 w1, 9 b1, 10 w2, 11 b2, 12 out_w, 13 out_b
// ---------------------------------------------------------------------------
extern "C" void kernel_launch(void* const* d_in, const int* in_sizes, int n_in,
                              void* d_out, int out_size)
{
    const int*   seq    = (const int*)  d_in[0];
    const float* embed  = (const float*)d_in[1];
    const float* ff_w1  = (const float*)d_in[2];
    const float* ff_b1  = (const float*)d_in[3];
    const float* ff_w2  = (const float*)d_in[4];
    const float* ff_b2  = (const float*)d_in[5];
    const float* ln_g   = (const float*)d_in[6];
    const float* ln_b   = (const float*)d_in[7];
    const float* w1     = (const float*)d_in[8];
    const float* b1     = (const float*)d_in[9];
    const float* w2     = (const float*)d_in[10];
    const float* b2     = (const float*)d_in[11];
    const float* out_w  = (const float*)d_in[12];
    const float* out_b  = (const float*)d_in[13];
    float*       out    = (float*)d_out;

    build_table_kernel<<<64, 128>>>(embed, ff_w1, ff_b1, ff_w2, ff_b2, ln_g, ln_b);
    gram_kernel<<<64, 64>>>();
    ttt_kernel<<<256 / CPB, NTHR>>>(seq, w1, b1, w2, b2, out_w, out_b, out);
}